// round 15
// baseline (speedup 1.0000x reference)
#include <cuda_runtime.h>

#define N_NODES 50000
#define N_EDGES 800000
#define DIM_IN  128
#define DD      256
#define D_OUT   64
#define NLAYERS 3

typedef unsigned long long u64;

// ---------------- scratch (device globals; no allocations) ----------------
__device__ float g_hn [N_NODES * DD];   // layernormed activations (the only h)
__device__ float g_agg[N_NODES * DD];   // masked aggregation buffer
__device__ __align__(16) float g_pr[N_NODES * 8]; // [p_in0,p_in1,p_out0,p_out1,r_in0,r_in1,r_out0,r_out1]
__device__ int   g_rowptr[N_NODES + 1];
__device__ int   g_off[N_NODES];
__device__ int   g_cnt[N_NODES];
__device__ int   g_col[N_EDGES];
__device__ unsigned char g_in0 [N_NODES];
__device__ unsigned char g_out0[N_NODES];
__device__ int   g_perm[N_NODES];       // active nodes first, inactive after
__device__ int   g_nact;
__device__ int   g_ntail;

// ---------------- helpers ----------------
__device__ __forceinline__ u64 dup2(float x) {
    u64 r; unsigned u = __float_as_uint(x);
    asm("mov.b64 %0, {%1, %1};" : "=l"(r) : "r"(u));
    return r;
}
__device__ __forceinline__ float2 up2(u64 v) {
    unsigned lo, hi;
    asm("mov.b64 {%0, %1}, %2;" : "=r"(lo), "=r"(hi) : "l"(v));
    return make_float2(__uint_as_float(lo), __uint_as_float(hi));
}
__device__ __forceinline__ u64 pk2(float x, float y) {
    u64 r;
    asm("mov.b64 %0, {%1, %2};" : "=l"(r)
        : "r"(__float_as_uint(x)), "r"(__float_as_uint(y)));
    return r;
}
__device__ __forceinline__ void ffma2(u64& d, u64 a, u64 b) {
    asm("fma.rn.f32x2 %0, %1, %2, %0;" : "+l"(d) : "l"(a), "l"(b));
}
__device__ __forceinline__ float wsum(float v) {
    #pragma unroll
    for (int o = 16; o; o >>= 1) v += __shfl_xor_sync(0xffffffffu, v, o);
    return v;
}

// ---------------- CSR build ----------------
__global__ void k_hist(const int* __restrict__ ei) {
    int e = blockIdx.x * blockDim.x + threadIdx.x;
    if (e < N_EDGES) atomicAdd(&g_cnt[ei[e]], 1);
}
__global__ void k_scan() {
    __shared__ int s[1024];
    __shared__ int carry;
    int tid = threadIdx.x;
    if (tid == 0) carry = 0;
    __syncthreads();
    for (int start = 0; start < N_NODES; start += 1024) {
        int i = start + tid;
        int v = (i < N_NODES) ? g_cnt[i] : 0;
        s[tid] = v;
        __syncthreads();
        for (int o = 1; o < 1024; o <<= 1) {
            int t = (tid >= o) ? s[tid - o] : 0;
            __syncthreads();
            s[tid] += t;
            __syncthreads();
        }
        int base = carry;
        int excl = base + s[tid] - v;
        if (i < N_NODES) { g_rowptr[i] = excl; g_off[i] = excl; }
        int tot = s[1023];
        __syncthreads();
        if (tid == 0) carry = base + tot;
        __syncthreads();
    }
    if (threadIdx.x == 0) g_rowptr[N_NODES] = carry;
}
__global__ void k_scatter(const int* __restrict__ ei) {
    int e = blockIdx.x * blockDim.x + threadIdx.x;
    if (e < N_EDGES) {
        int u = ei[e];
        int v = ei[N_EDGES + e];
        int p = atomicAdd(&g_off[u], 1);
        g_col[p] = v;
    }
}

// ---------------- per-node action projections (8 scalars/node) ----------------
// Also resets the partition counters used by the following k_decide.
__global__ void __launch_bounds__(256)
k_act(const float* __restrict__ Wir, const float* __restrict__ Wia,
      const float* __restrict__ Wor, const float* __restrict__ Woa) {
    if (blockIdx.x == 0 && threadIdx.x == 0) { g_nact = 0; g_ntail = 0; }
    __shared__ float sW[8][DD];
    int tid = threadIdx.x;
    for (int j = tid; j < 2048; j += 256) {
        int which = j >> 9;             // 0:Wia 1:Woa 2:Wir 3:Wor
        int rem = j & 511;
        int k = rem >> 1, c = rem & 1;
        const float* src = (which == 0) ? Wia : (which == 1) ? Woa
                          : (which == 2) ? Wir : Wor;
        sW[which * 2 + c][k] = src[k * 2 + c];
    }
    __syncthreads();
    int lane = tid & 31;
    float wr[64];
    #pragma unroll
    for (int o = 0; o < 8; o++)
        #pragma unroll
        for (int i = 0; i < 8; i++)
            wr[o * 8 + i] = sW[o][lane + 32 * i];

    for (int node = blockIdx.x * 8 + (tid >> 5); node < N_NODES;
         node += gridDim.x * 8) {
        const float* hr = g_hn + (size_t)node * DD;
        float z[8];
        #pragma unroll
        for (int o = 0; o < 8; o++) z[o] = 0.f;
        #pragma unroll
        for (int i = 0; i < 8; i++) {
            float hv = hr[lane + 32 * i];
            #pragma unroll
            for (int o = 0; o < 8; o++) z[o] += hv * wr[o * 8 + i];
        }
        #pragma unroll
        for (int o = 0; o < 8; o++) z[o] = wsum(z[o]);
        if (lane == 0) {
            float* dst = g_pr + (size_t)node * 8;
            #pragma unroll
            for (int o = 0; o < 8; o++) dst[o] = z[o];
        }
    }
}

// ---------------- decisions + partition (fused) ----------------
// temp is a positive scalar -> never changes argmax; (hard+y-y) == hard to 2^-22.
// Partition order within active/inactive groups is arbitrary: per-row GEMM work
// is independent, g_nact is order-invariant, and the boundary block computes
// full K for its inactive rows against exactly-zero agg rows -> deterministic.
__global__ void k_decide(const float* __restrict__ bin,
                         const float* __restrict__ bout,
                         const float* __restrict__ gl) {
    int u = blockIdx.x * blockDim.x + threadIdx.x;
    bool valid = (u < N_NODES);
    bool act = false;
    if (valid) {
        float sx = 0.f, sy = 0.f, sz = 0.f, sw = 0.f;
        int e0 = g_rowptr[u], e1 = g_rowptr[u + 1];
        for (int j = e0; j < e1; j++) {
            int v = g_col[j];
            float4 p = *(const float4*)(g_pr + (size_t)v * 8);
            sx += p.x; sy += p.y; sz += p.z; sw += p.w;
        }
        float4 r = *(const float4*)(g_pr + (size_t)u * 8 + 4);
        float a0 = r.x + sx + bin[0]  + gl[(size_t)u * 2 + 0];
        float a1 = r.y + sy + bin[1]  + gl[(size_t)u * 2 + 1];
        act = (a0 >= a1);                  // argmax ties -> first index
        g_in0[u] = act ? 1 : 0;
        float c0 = r.z + sz + bout[0] + gl[(size_t)2 * N_NODES + (size_t)u * 2 + 0];
        float c1 = r.w + sw + bout[1] + gl[(size_t)2 * N_NODES + (size_t)u * 2 + 1];
        g_out0[u] = (c0 >= c1) ? 1 : 0;
    }
    unsigned ma = __ballot_sync(0xffffffffu, valid && act);
    unsigned mi = __ballot_sync(0xffffffffu, valid && !act);
    int lane = threadIdx.x & 31;
    int na = __popc(ma), ni = __popc(mi);
    int ra = __popc(ma & ((1u << lane) - 1));
    int ri = __popc(mi & ((1u << lane) - 1));
    int base_a, base_i;
    if (lane == 0) base_a = atomicAdd(&g_nact, na);
    if (lane == 1) base_i = atomicAdd(&g_ntail, ni);
    base_a = __shfl_sync(0xffffffffu, base_a, 0);
    base_i = __shfl_sync(0xffffffffu, base_i, 1);
    if (valid) {
        if (act) g_perm[base_a + ra] = u;
        else     g_perm[N_NODES - 1 - (base_i + ri)] = u;
    }
}

// ---------------- masked aggregation (warp per node, CSR gather) ----------------
__global__ void k_agg_masked() {
    int u = (blockIdx.x * blockDim.x + threadIdx.x) >> 5;
    if (u >= N_NODES) return;
    int lane = threadIdx.x & 31;
    float4 a0 = make_float4(0.f, 0.f, 0.f, 0.f);
    float4 a1 = make_float4(0.f, 0.f, 0.f, 0.f);
    if (g_in0[u]) {
        int s = g_rowptr[u], e = g_rowptr[u + 1];
        for (int j = s; j < e; j++) {
            int v = g_col[j];
            if (!g_out0[v]) continue;
            const float4* p = (const float4*)(g_hn + (size_t)v * DD);
            float4 x0 = p[lane], x1 = p[lane + 32];
            a0.x += x0.x; a0.y += x0.y; a0.z += x0.z; a0.w += x0.w;
            a1.x += x1.x; a1.y += x1.y; a1.z += x1.z; a1.w += x1.w;
        }
    }
    float4* q = (float4*)(g_agg + (size_t)u * DD);
    q[lane] = a0; q[lane + 32] = a1;
}

// ---------------- SGEMM (FFMA2) fused bias+ReLU+LN, permuted rows, K-gated ----
// hn[perm] = LN( relu( [A1|A2][perm] @ [B1;B2] + bias ) )
// BM=64, BN=256(=Nc), BK=16, double-buffered smem (1 sync per k-tile).
// GATED: blocks fully inside the inactive region (brow0 >= g_nact) skip the A2
// k-range (agg rows there are exactly zero).
template <int GATED>
__global__ void __launch_bounds__(256, 2)
sgemm_ln(const float* __restrict__ A1, const float* __restrict__ A2,
         int K1, int K2,
         const float* __restrict__ B1, const float* __restrict__ B2,
         const float* __restrict__ bias,
         const float* __restrict__ gw, const float* __restrict__ gb,
         float* __restrict__ C, int M, int use_perm) {
    const int BM = 64, BN = 256, BK = 16, TM = 8, TN = 8;
    __shared__ __align__(16) float As[2][BK][BM + 4];
    __shared__ __align__(16) float Bs[2][BK][BN];
    __shared__ int sPerm[BM];
    __shared__ int sNt;

    int tid = threadIdx.x;
    int brow0 = blockIdx.x * BM;
    int tx = tid & 31, ty = tid >> 5;        // warp = fixed ty -> 8 rows
    int m0 = ty * TM, n0 = tx * TN;
    int t1 = K1 / BK;

    if (tid < BM) {
        int gi = brow0 + tid;
        sPerm[tid] = (gi < M) ? (use_perm ? g_perm[gi] : gi) : -1;
    }
    if (tid == 0) {
        int full = (K1 + K2) / BK;
        sNt = (GATED && brow0 >= g_nact) ? t1 : full;
    }
    __syncthreads();
    int nt = sNt;

    float4 ar; float4 br[4];
    u64 acc[TM][TN / 2];
    #pragma unroll
    for (int i = 0; i < TM; i++)
        #pragma unroll
        for (int j = 0; j < TN / 2; j++) acc[i][j] = 0ull;

#define LOAD_TILE(KT) {                                                        \
    const float* Ap; int lda, kofs;                                            \
    if ((KT) < t1) { Ap = A1; lda = K1; kofs = (KT) * BK; }                    \
    else           { Ap = A2; lda = K2; kofs = (KT) * BK - K1; }               \
    {                                                                          \
        int r = tid >> 2, c4 = tid & 3;                                        \
        int gr = sPerm[r];                                                     \
        ar = (gr >= 0)                                                         \
           ? *(const float4*)(Ap + (size_t)gr * lda + kofs + c4 * 4)           \
           : make_float4(0.f, 0.f, 0.f, 0.f);                                  \
    }                                                                          \
    const float* Bp = ((KT) < t1) ? B1 : B2;                                   \
    int bk0 = ((KT) < t1) ? (KT) * BK : (KT) * BK - K1;                        \
    for (int i = 0; i < 4; i++) {                                              \
        int idx = tid + i * 256;                                               \
        int r = idx >> 6, c4 = idx & 63;                                       \
        br[i] = *(const float4*)(Bp + (size_t)(bk0 + r) * BN + c4 * 4);        \
    }                                                                          \
}

#define STORE_TILE(S) {                                                        \
    int r = tid >> 2, c4 = tid & 3;                                            \
    As[S][c4 * 4 + 0][r] = ar.x;                                               \
    As[S][c4 * 4 + 1][r] = ar.y;                                               \
    As[S][c4 * 4 + 2][r] = ar.z;                                               \
    As[S][c4 * 4 + 3][r] = ar.w;                                               \
    for (int i = 0; i < 4; i++) {                                              \
        int idx = tid + i * 256;                                               \
        int rr = idx >> 6, cc = idx & 63;                                      \
        *(float4*)(&Bs[S][rr][cc * 4]) = br[i];                                \
    }                                                                          \
}

    LOAD_TILE(0);
    STORE_TILE(0);
    __syncthreads();

    for (int kt = 0; kt < nt; kt++) {
        int sb = kt & 1;
        if (kt + 1 < nt) { LOAD_TILE(kt + 1); }
        #pragma unroll
        for (int k = 0; k < BK; k++) {
            float4 av0 = *(const float4*)(&As[sb][k][m0]);
            float4 av1 = *(const float4*)(&As[sb][k][m0 + 4]);
            ulonglong2 bv0 = *(const ulonglong2*)(&Bs[sb][k][n0]);
            ulonglong2 bv1 = *(const ulonglong2*)(&Bs[sb][k][n0 + 4]);
            u64 b2[4] = {bv0.x, bv0.y, bv1.x, bv1.y};
            float a[8] = {av0.x, av0.y, av0.z, av0.w, av1.x, av1.y, av1.z, av1.w};
            #pragma unroll
            for (int i = 0; i < TM; i++) {
                u64 a2 = dup2(a[i]);
                #pragma unroll
                for (int j = 0; j < TN / 2; j++) ffma2(acc[i][j], a2, b2[j]);
            }
        }
        if (kt + 1 < nt) {
            STORE_TILE(1 - sb);
            __syncthreads();
        }
    }
#undef LOAD_TILE
#undef STORE_TILE

    // ---- epilogue: bias + relu + LayerNorm (single-pass mean/var) ----
    float4 bi0 = *(const float4*)(bias + n0);
    float4 bi1 = *(const float4*)(bias + n0 + 4);
    float bb[8] = {bi0.x, bi0.y, bi0.z, bi0.w, bi1.x, bi1.y, bi1.z, bi1.w};
    float4 gg0 = *(const float4*)(gw + n0);
    float4 gg1 = *(const float4*)(gw + n0 + 4);
    float gv[8] = {gg0.x, gg0.y, gg0.z, gg0.w, gg1.x, gg1.y, gg1.z, gg1.w};
    float4 lb0 = *(const float4*)(gb + n0);
    float4 lb1 = *(const float4*)(gb + n0 + 4);
    float lbv[8] = {lb0.x, lb0.y, lb0.z, lb0.w, lb1.x, lb1.y, lb1.z, lb1.w};

    float o[TM][TN];
    #pragma unroll
    for (int i = 0; i < TM; i++) {
        #pragma unroll
        for (int j = 0; j < TN / 2; j++) {
            float2 p = up2(acc[i][j]);
            o[i][2 * j] = p.x; o[i][2 * j + 1] = p.y;
        }
        #pragma unroll
        for (int j = 0; j < TN; j++)
            o[i][j] = fmaxf(o[i][j] + bb[j], 0.f);
    }

    #pragma unroll
    for (int i = 0; i < TM; i++) {
        float s = 0.f, q = 0.f;
        #pragma unroll
        for (int j = 0; j < TN; j++) { s += o[i][j]; q += o[i][j] * o[i][j]; }
        s = wsum(s); q = wsum(q);
        float mean = s * (1.0f / DD);
        float var = q * (1.0f / DD) - mean * mean;
        float rstd = rsqrtf(var + 1e-5f);
        int gr = sPerm[m0 + i];
        if (gr >= 0) {
            float4 s0, s1;
            s0.x = (o[i][0] - mean) * rstd * gv[0] + lbv[0];
            s0.y = (o[i][1] - mean) * rstd * gv[1] + lbv[1];
            s0.z = (o[i][2] - mean) * rstd * gv[2] + lbv[2];
            s0.w = (o[i][3] - mean) * rstd * gv[3] + lbv[3];
            s1.x = (o[i][4] - mean) * rstd * gv[4] + lbv[4];
            s1.y = (o[i][5] - mean) * rstd * gv[5] + lbv[5];
            s1.z = (o[i][6] - mean) * rstd * gv[6] + lbv[6];
            s1.w = (o[i][7] - mean) * rstd * gv[7] + lbv[7];
            float* dst = C + (size_t)gr * BN + n0;
            *(float4*)(dst)     = s0;
            *(float4*)(dst + 4) = s1;
        }
    }
}

// ---------------- plain SGEMM (decoder, no LN) ----------------
template <int BN, int TN, int RELU>
__global__ void __launch_bounds__(256, 2)
sgemm_dual(const float* __restrict__ A1, const float* __restrict__ A2,
           int K1, int K2,
           const float* __restrict__ B1, const float* __restrict__ B2,
           const float* __restrict__ bias, float* __restrict__ C,
           int M, int Nc) {
    const int BM = 128, BK = 16, TM = 8;
    const int NB4  = BN / 4;
    const int A_LD = 2;
    const int B_LD = (BK * BN / 4) / 256;
    __shared__ __align__(16) float As[BK][BM + 4];
    __shared__ __align__(16) float Bs[BK][BN];

    int tid = threadIdx.x;
    int brow0 = blockIdx.y * BM, bcol0 = blockIdx.x * BN;
    int tx = tid % (BN / TN), ty = tid / (BN / TN);
    int m0 = ty * TM, n0 = tx * TN;
    int t1 = K1 / BK, nt = (K1 + K2) / BK;

    float4 ar[A_LD], br[B_LD];
    u64 acc[TM][TN / 2];
    #pragma unroll
    for (int i = 0; i < TM; i++)
        #pragma unroll
        for (int j = 0; j < TN / 2; j++) acc[i][j] = 0ull;

#define LOAD_TILE(KT) {                                                        \
    const float* Ap; int lda, kofs;                                            \
    if ((KT) < t1) { Ap = A1; lda = K1; kofs = (KT) * BK; }                    \
    else           { Ap = A2; lda = K2; kofs = (KT) * BK - K1; }               \
    for (int i = 0; i < A_LD; i++) {                                           \
        int idx = tid + i * 256;                                               \
        int r = idx >> 2, c4 = idx & 3;                                        \
        int gr = brow0 + r;                                                    \
        ar[i] = (gr < M)                                                       \
              ? *(const float4*)(Ap + (size_t)gr * lda + kofs + c4 * 4)        \
              : make_float4(0.f, 0.f, 0.f, 0.f);                               \
    }                                                                          \
    const float* Bp = ((KT) < t1) ? B1 : B2;                                   \
    int bk0 = ((KT) < t1) ? (KT) * BK : (KT) * BK - K1;                        \
    for (int i = 0; i < B_LD; i++) {                                           \
        int idx = tid + i * 256;                                               \
        int r = idx / NB4, c4 = idx % NB4;                                     \
        br[i] = *(const float4*)(Bp + (size_t)(bk0 + r) * Nc + bcol0 + c4 * 4);\
    }                                                                          \
}

    LOAD_TILE(0);
    for (int kt = 0; kt < nt; kt++) {
        #pragma unroll
        for (int i = 0; i < A_LD; i++) {
            int idx = tid + i * 256;
            int r = idx >> 2, c4 = idx & 3;
            As[c4 * 4 + 0][r] = ar[i].x;
            As[c4 * 4 + 1][r] = ar[i].y;
            As[c4 * 4 + 2][r] = ar[i].z;
            As[c4 * 4 + 3][r] = ar[i].w;
        }
        #pragma unroll
        for (int i = 0; i < B_LD; i++) {
            int idx = tid + i * 256;
            int r = idx / NB4, c4 = idx % NB4;
            *(float4*)(&Bs[r][c4 * 4]) = br[i];
        }
        __syncthreads();
        if (kt + 1 < nt) { LOAD_TILE(kt + 1); }
        #pragma unroll
        for (int k = 0; k < BK; k++) {
            float4 av0 = *(const float4*)(&As[k][m0]);
            float4 av1 = *(const float4*)(&As[k][m0 + 4]);
            u64 b2[TN / 2];
            #pragma unroll
            for (int j = 0; j < TN / 4; j++) {
                float4 bv = *(const float4*)(&Bs[k][n0 + 4 * j]);
                b2[2 * j]     = pk2(bv.x, bv.y);
                b2[2 * j + 1] = pk2(bv.z, bv.w);
            }
            float a[8] = {av0.x, av0.y, av0.z, av0.w, av1.x, av1.y, av1.z, av1.w};
            #pragma unroll
            for (int i = 0; i < TM; i++) {
                u64 a2 = dup2(a[i]);
                #pragma unroll
                for (int j = 0; j < TN / 2; j++) ffma2(acc[i][j], a2, b2[j]);
            }
        }
        __syncthreads();
    }
#undef LOAD_TILE

    #pragma unroll
    for (int i = 0; i < TM; i++) {
        int gr = brow0 + m0 + i;
        if (gr < M) {
            float o[TN];
            #pragma unroll
            for (int j = 0; j < TN / 2; j++) {
                float2 p = up2(acc[i][j]);
                o[2 * j] = p.x; o[2 * j + 1] = p.y;
            }
            #pragma unroll
            for (int j = 0; j < TN; j++) {
                float v = o[j] + bias[bcol0 + n0 + j];
                if (RELU) v = fmaxf(v, 0.f);
                o[j] = v;
            }
            #pragma unroll
            for (int j = 0; j < TN / 4; j++) {
                float4 st = make_float4(o[4 * j], o[4 * j + 1],
                                        o[4 * j + 2], o[4 * j + 3]);
                *(float4*)(C + (size_t)gr * Nc + bcol0 + n0 + 4 * j) = st;
            }
        }
    }
}

// ---------------- launch ----------------
extern "C" void kernel_launch(void* const* d_in, const int* in_sizes, int n_in,
                              void* d_out, int out_size) {
    const float* x      = (const float*)d_in[0];
    const int*   ei     = (const int*)  d_in[1];
    const float* gum    = (const float*)d_in[2];
    const float* W_enc  = (const float*)d_in[3];
    const float* b_enc  = (const float*)d_in[4];
    const float* W_root = (const float*)d_in[5];
    const float* W_agg  = (const float*)d_in[6];
    const float* b_env  = (const float*)d_in[7];
    const float* Wir    = (const float*)d_in[8];
    const float* Wia    = (const float*)d_in[9];
    const float* bin    = (const float*)d_in[10];
    const float* Wor    = (const float*)d_in[11];
    const float* Woa    = (const float*)d_in[12];
    const float* bout   = (const float*)d_in[13];
    // d_in[14..16] = Wt_r, Wt_a, b_t : unused (temperature never affects argmax)
    const float* ln_g   = (const float*)d_in[17];
    const float* ln_b   = (const float*)d_in[18];
    const float* W_dec  = (const float*)d_in[19];
    const float* b_dec  = (const float*)d_in[20];
    float* out = (float*)d_out;

    void *phn, *pagg, *pcnt;
    cudaGetSymbolAddress(&phn,  g_hn);
    cudaGetSymbolAddress(&pagg, g_agg);
    cudaGetSymbolAddress(&pcnt, g_cnt);
    float* hnbuf  = (float*)phn;
    float* aggbuf = (float*)pagg;

    const int EB = (N_EDGES + 255) / 256;
    const int WB = (N_NODES + 7) / 8;          // warp-per-node kernels, 256 thr
    const int NB = (N_NODES + 255) / 256;
    const int GEMM_B = (N_NODES + 63) / 64;    // 782

    // CSR build (memset replaces the zeroing kernel; also shifts ncu sampling)
    cudaMemsetAsync(pcnt, 0, N_NODES * sizeof(int));
    k_hist<<<EB, 256>>>(ei);
    k_scan<<<1, 1024>>>();
    k_scatter<<<EB, 256>>>(ei);

    // encoder: hn = LN(relu(x @ W_enc + b_enc))   (identity row order)
    sgemm_ln<0><<<GEMM_B, 256>>>(x, nullptr, DIM_IN, 0,
                                 W_enc, nullptr, b_enc, ln_g, ln_b,
                                 hnbuf, N_NODES, /*use_perm=*/0);

    for (int l = 0; l < NLAYERS; l++) {
        k_act<<<296, 256>>>(Wir, Wia, Wor, Woa);   // also resets partition ctrs
        k_decide<<<NB, 256>>>(bin, bout, gum + (size_t)l * 2 * N_NODES * 2);
        k_agg_masked<<<WB, 256>>>();
        // hn = LN(relu([hn|agg] @ [W_root;W_agg] + b_env)), permuted + K-gated
        sgemm_ln<1><<<GEMM_B, 256>>>(hnbuf, aggbuf, DD, DD,
                                     W_root + (size_t)l * DD * DD,
                                     W_agg  + (size_t)l * DD * DD,
                                     b_env  + (size_t)l * DD, ln_g, ln_b,
                                     hnbuf, N_NODES, /*use_perm=*/1);
    }

    // decoder: out = hn @ W_dec + b_dec
    sgemm_dual<64, 4, 0><<<dim3(1, (N_NODES + 127) / 128), 256>>>(
        hnbuf, nullptr, DD, 0, W_dec, nullptr, b_dec, out, N_NODES, D_OUT);
}

// round 16
// speedup vs baseline: 1.0722x; 1.0722x over previous
#include <cuda_runtime.h>

#define N_NODES 50000
#define N_EDGES 800000
#define DIM_IN  128
#define DD      256
#define D_OUT   64
#define NLAYERS 3

typedef unsigned long long u64;

// ---------------- scratch (device globals; no allocations) ----------------
__device__ float g_hn [N_NODES * DD];   // layernormed activations (the only h)
__device__ float g_agg[N_NODES * DD];   // masked aggregation buffer
__device__ __align__(16) float g_pr[N_NODES * 8]; // [p_in0,p_in1,p_out0,p_out1,r_in0,r_in1,r_out0,r_out1]
__device__ int   g_rowptr[N_NODES + 1];
__device__ int   g_off[N_NODES];
__device__ int   g_cnt[N_NODES];
__device__ int   g_col[N_EDGES];
__device__ unsigned char g_in0 [N_NODES];
__device__ unsigned char g_out0[N_NODES];
__device__ int   g_perm[N_NODES];       // active nodes first, inactive after
__device__ int   g_nact;
__device__ int   g_ntail;

// ---------------- helpers ----------------
__device__ __forceinline__ u64 dup2(float x) {
    u64 r; unsigned u = __float_as_uint(x);
    asm("mov.b64 %0, {%1, %1};" : "=l"(r) : "r"(u));
    return r;
}
__device__ __forceinline__ float2 up2(u64 v) {
    unsigned lo, hi;
    asm("mov.b64 {%0, %1}, %2;" : "=r"(lo), "=r"(hi) : "l"(v));
    return make_float2(__uint_as_float(lo), __uint_as_float(hi));
}
__device__ __forceinline__ u64 pk2(float x, float y) {
    u64 r;
    asm("mov.b64 %0, {%1, %2};" : "=l"(r)
        : "r"(__float_as_uint(x)), "r"(__float_as_uint(y)));
    return r;
}
__device__ __forceinline__ void ffma2(u64& d, u64 a, u64 b) {
    asm("fma.rn.f32x2 %0, %1, %2, %0;" : "+l"(d) : "l"(a), "l"(b));
}
__device__ __forceinline__ float wsum(float v) {
    #pragma unroll
    for (int o = 16; o; o >>= 1) v += __shfl_xor_sync(0xffffffffu, v, o);
    return v;
}

// ---------------- CSR build ----------------
__global__ void k_hist(const int* __restrict__ ei) {
    int e = blockIdx.x * blockDim.x + threadIdx.x;
    if (e < N_EDGES) atomicAdd(&g_cnt[ei[e]], 1);
}
__global__ void k_scan() {
    __shared__ int s[1024];
    __shared__ int carry;
    int tid = threadIdx.x;
    if (tid == 0) carry = 0;
    __syncthreads();
    for (int start = 0; start < N_NODES; start += 1024) {
        int i = start + tid;
        int v = (i < N_NODES) ? g_cnt[i] : 0;
        s[tid] = v;
        __syncthreads();
        for (int o = 1; o < 1024; o <<= 1) {
            int t = (tid >= o) ? s[tid - o] : 0;
            __syncthreads();
            s[tid] += t;
            __syncthreads();
        }
        int base = carry;
        int excl = base + s[tid] - v;
        if (i < N_NODES) { g_rowptr[i] = excl; g_off[i] = excl; }
        int tot = s[1023];
        __syncthreads();
        if (tid == 0) carry = base + tot;
        __syncthreads();
    }
    if (threadIdx.x == 0) g_rowptr[N_NODES] = carry;
}
__global__ void k_scatter(const int* __restrict__ ei) {
    int e = blockIdx.x * blockDim.x + threadIdx.x;
    if (e < N_EDGES) {
        int u = ei[e];
        int v = ei[N_EDGES + e];
        int p = atomicAdd(&g_off[u], 1);
        g_col[p] = v;
    }
}

// ---------------- per-node action projections (8 scalars/node) ----------------
// Also resets the partition counters used by the following k_decide.
__global__ void __launch_bounds__(256)
k_act(const float* __restrict__ Wir, const float* __restrict__ Wia,
      const float* __restrict__ Wor, const float* __restrict__ Woa) {
    if (blockIdx.x == 0 && threadIdx.x == 0) { g_nact = 0; g_ntail = 0; }
    __shared__ float sW[8][DD];
    int tid = threadIdx.x;
    for (int j = tid; j < 2048; j += 256) {
        int which = j >> 9;             // 0:Wia 1:Woa 2:Wir 3:Wor
        int rem = j & 511;
        int k = rem >> 1, c = rem & 1;
        const float* src = (which == 0) ? Wia : (which == 1) ? Woa
                          : (which == 2) ? Wir : Wor;
        sW[which * 2 + c][k] = src[k * 2 + c];
    }
    __syncthreads();
    int lane = tid & 31;
    float wr[64];
    #pragma unroll
    for (int o = 0; o < 8; o++)
        #pragma unroll
        for (int i = 0; i < 8; i++)
            wr[o * 8 + i] = sW[o][lane + 32 * i];

    for (int node = blockIdx.x * 8 + (tid >> 5); node < N_NODES;
         node += gridDim.x * 8) {
        const float* hr = g_hn + (size_t)node * DD;
        float z[8];
        #pragma unroll
        for (int o = 0; o < 8; o++) z[o] = 0.f;
        #pragma unroll
        for (int i = 0; i < 8; i++) {
            float hv = hr[lane + 32 * i];
            #pragma unroll
            for (int o = 0; o < 8; o++) z[o] += hv * wr[o * 8 + i];
        }
        #pragma unroll
        for (int o = 0; o < 8; o++) z[o] = wsum(z[o]);
        if (lane == 0) {
            float* dst = g_pr + (size_t)node * 8;
            #pragma unroll
            for (int o = 0; o < 8; o++) dst[o] = z[o];
        }
    }
}

// ---------------- decisions + partition (fused) ----------------
// temp is a positive scalar -> never changes argmax; (hard+y-y) == hard to 2^-22.
// Partition order within active/inactive groups is arbitrary: per-row GEMM work
// is independent, g_nact is order-invariant, and the boundary block computes
// full K for its inactive rows against exactly-zero agg rows -> deterministic.
__global__ void k_decide(const float* __restrict__ bin,
                         const float* __restrict__ bout,
                         const float* __restrict__ gl) {
    int u = blockIdx.x * blockDim.x + threadIdx.x;
    bool valid = (u < N_NODES);
    bool act = false;
    if (valid) {
        float sx = 0.f, sy = 0.f, sz = 0.f, sw = 0.f;
        int e0 = g_rowptr[u], e1 = g_rowptr[u + 1];
        for (int j = e0; j < e1; j++) {
            int v = g_col[j];
            float4 p = *(const float4*)(g_pr + (size_t)v * 8);
            sx += p.x; sy += p.y; sz += p.z; sw += p.w;
        }
        float4 r = *(const float4*)(g_pr + (size_t)u * 8 + 4);
        float a0 = r.x + sx + bin[0]  + gl[(size_t)u * 2 + 0];
        float a1 = r.y + sy + bin[1]  + gl[(size_t)u * 2 + 1];
        act = (a0 >= a1);                  // argmax ties -> first index
        g_in0[u] = act ? 1 : 0;
        float c0 = r.z + sz + bout[0] + gl[(size_t)2 * N_NODES + (size_t)u * 2 + 0];
        float c1 = r.w + sw + bout[1] + gl[(size_t)2 * N_NODES + (size_t)u * 2 + 1];
        g_out0[u] = (c0 >= c1) ? 1 : 0;
    }
    unsigned ma = __ballot_sync(0xffffffffu, valid && act);
    unsigned mi = __ballot_sync(0xffffffffu, valid && !act);
    int lane = threadIdx.x & 31;
    int na = __popc(ma), ni = __popc(mi);
    int ra = __popc(ma & ((1u << lane) - 1));
    int ri = __popc(mi & ((1u << lane) - 1));
    int base_a, base_i;
    if (lane == 0) base_a = atomicAdd(&g_nact, na);
    if (lane == 1) base_i = atomicAdd(&g_ntail, ni);
    base_a = __shfl_sync(0xffffffffu, base_a, 0);
    base_i = __shfl_sync(0xffffffffu, base_i, 1);
    if (valid) {
        if (act) g_perm[base_a + ra] = u;
        else     g_perm[N_NODES - 1 - (base_i + ri)] = u;
    }
}

// ---------------- masked aggregation (warp per node, CSR gather) ----------------
__global__ void k_agg_masked() {
    int u = (blockIdx.x * blockDim.x + threadIdx.x) >> 5;
    if (u >= N_NODES) return;
    int lane = threadIdx.x & 31;
    float4 a0 = make_float4(0.f, 0.f, 0.f, 0.f);
    float4 a1 = make_float4(0.f, 0.f, 0.f, 0.f);
    if (g_in0[u]) {
        int s = g_rowptr[u], e = g_rowptr[u + 1];
        for (int j = s; j < e; j++) {
            int v = g_col[j];
            if (!g_out0[v]) continue;
            const float4* p = (const float4*)(g_hn + (size_t)v * DD);
            float4 x0 = p[lane], x1 = p[lane + 32];
            a0.x += x0.x; a0.y += x0.y; a0.z += x0.z; a0.w += x0.w;
            a1.x += x1.x; a1.y += x1.y; a1.z += x1.z; a1.w += x1.w;
        }
    }
    float4* q = (float4*)(g_agg + (size_t)u * DD);
    q[lane] = a0; q[lane + 32] = a1;
}

// ---------------- SGEMM (FFMA2) fused bias+ReLU+LN, permuted rows, K-gated ----
// hn[perm] = LN( relu( [A1|A2][perm] @ [B1;B2] + bias ) )
// BM=64, BN=256(=Nc), BK=16, double-buffered smem.
// Thread column mapping: lane owns cols {4*tx..4*tx+3} U {128+4*tx..128+4*tx+3}
// -> both B LDS.128 have 16B lane stride = conflict-free (was 32B stride, 2-way).
// GATED: blocks fully inside the inactive region (brow0 >= g_nact) skip the A2
// k-range (agg rows there are exactly zero).
template <int GATED>
__global__ void __launch_bounds__(256, 2)
sgemm_ln(const float* __restrict__ A1, const float* __restrict__ A2,
         int K1, int K2,
         const float* __restrict__ B1, const float* __restrict__ B2,
         const float* __restrict__ bias,
         const float* __restrict__ gw, const float* __restrict__ gb,
         float* __restrict__ C, int M, int use_perm) {
    const int BM = 64, BN = 256, BK = 16, TM = 8, TN = 8;
    __shared__ __align__(16) float As[2][BK][BM + 4];
    __shared__ __align__(16) float Bs[2][BK][BN];
    __shared__ int sPerm[BM];
    __shared__ int sNt;

    int tid = threadIdx.x;
    int brow0 = blockIdx.x * BM;
    int tx = tid & 31, ty = tid >> 5;        // warp = fixed ty -> 8 rows
    int m0 = ty * TM;
    int n0a = tx * 4;                        // first 4-col group
    int n0b = 128 + tx * 4;                  // second 4-col group
    int t1 = K1 / BK;

    if (tid < BM) {
        int gi = brow0 + tid;
        sPerm[tid] = (gi < M) ? (use_perm ? g_perm[gi] : gi) : -1;
    }
    if (tid == 0) {
        int full = (K1 + K2) / BK;
        sNt = (GATED && brow0 >= g_nact) ? t1 : full;
    }
    __syncthreads();
    int nt = sNt;

    float4 ar; float4 br[4];
    u64 acc[TM][TN / 2];
    #pragma unroll
    for (int i = 0; i < TM; i++)
        #pragma unroll
        for (int j = 0; j < TN / 2; j++) acc[i][j] = 0ull;

#define LOAD_TILE(KT) {                                                        \
    const float* Ap; int lda, kofs;                                            \
    if ((KT) < t1) { Ap = A1; lda = K1; kofs = (KT) * BK; }                    \
    else           { Ap = A2; lda = K2; kofs = (KT) * BK - K1; }               \
    {                                                                          \
        int r = tid >> 2, c4 = tid & 3;                                        \
        int gr = sPerm[r];                                                     \
        ar = (gr >= 0)                                                         \
           ? *(const float4*)(Ap + (size_t)gr * lda + kofs + c4 * 4)           \
           : make_float4(0.f, 0.f, 0.f, 0.f);                                  \
    }                                                                          \
    const float* Bp = ((KT) < t1) ? B1 : B2;                                   \
    int bk0 = ((KT) < t1) ? (KT) * BK : (KT) * BK - K1;                        \
    for (int i = 0; i < 4; i++) {                                              \
        int idx = tid + i * 256;                                               \
        int r = idx >> 6, c4 = idx & 63;                                       \
        br[i] = *(const float4*)(Bp + (size_t)(bk0 + r) * BN + c4 * 4);        \
    }                                                                          \
}

#define STORE_TILE(S) {                                                        \
    int r = tid >> 2, c4 = tid & 3;                                            \
    As[S][c4 * 4 + 0][r] = ar.x;                                               \
    As[S][c4 * 4 + 1][r] = ar.y;                                               \
    As[S][c4 * 4 + 2][r] = ar.z;                                               \
    As[S][c4 * 4 + 3][r] = ar.w;                                               \
    for (int i = 0; i < 4; i++) {                                              \
        int idx = tid + i * 256;                                               \
        int rr = idx >> 6, cc = idx & 63;                                      \
        *(float4*)(&Bs[S][rr][cc * 4]) = br[i];                                \
    }                                                                          \
}

    LOAD_TILE(0);
    STORE_TILE(0);
    __syncthreads();

    for (int kt = 0; kt < nt; kt++) {
        int sb = kt & 1;
        if (kt + 1 < nt) { LOAD_TILE(kt + 1); }
        #pragma unroll
        for (int k = 0; k < BK; k++) {
            float4 av0 = *(const float4*)(&As[sb][k][m0]);
            float4 av1 = *(const float4*)(&As[sb][k][m0 + 4]);
            ulonglong2 bv0 = *(const ulonglong2*)(&Bs[sb][k][n0a]);  // cols n0a..+3
            ulonglong2 bv1 = *(const ulonglong2*)(&Bs[sb][k][n0b]);  // cols n0b..+3
            u64 b2[4] = {bv0.x, bv0.y, bv1.x, bv1.y};
            float a[8] = {av0.x, av0.y, av0.z, av0.w, av1.x, av1.y, av1.z, av1.w};
            #pragma unroll
            for (int i = 0; i < TM; i++) {
                u64 a2 = dup2(a[i]);
                #pragma unroll
                for (int j = 0; j < TN / 2; j++) ffma2(acc[i][j], a2, b2[j]);
            }
        }
        if (kt + 1 < nt) {
            STORE_TILE(1 - sb);
            __syncthreads();
        }
    }
#undef LOAD_TILE
#undef STORE_TILE

    // ---- epilogue: bias + relu + LayerNorm (single-pass mean/var) ----
    // acc[i][0..1] -> cols n0a..n0a+3 ; acc[i][2..3] -> cols n0b..n0b+3
    float4 bi0 = *(const float4*)(bias + n0a);
    float4 bi1 = *(const float4*)(bias + n0b);
    float bb[8] = {bi0.x, bi0.y, bi0.z, bi0.w, bi1.x, bi1.y, bi1.z, bi1.w};
    float4 gg0 = *(const float4*)(gw + n0a);
    float4 gg1 = *(const float4*)(gw + n0b);
    float gv[8] = {gg0.x, gg0.y, gg0.z, gg0.w, gg1.x, gg1.y, gg1.z, gg1.w};
    float4 lb0 = *(const float4*)(gb + n0a);
    float4 lb1 = *(const float4*)(gb + n0b);
    float lbv[8] = {lb0.x, lb0.y, lb0.z, lb0.w, lb1.x, lb1.y, lb1.z, lb1.w};

    float o[TM][TN];
    #pragma unroll
    for (int i = 0; i < TM; i++) {
        #pragma unroll
        for (int j = 0; j < TN / 2; j++) {
            float2 p = up2(acc[i][j]);
            o[i][2 * j] = p.x; o[i][2 * j + 1] = p.y;
        }
        #pragma unroll
        for (int j = 0; j < TN; j++)
            o[i][j] = fmaxf(o[i][j] + bb[j], 0.f);
    }

    #pragma unroll
    for (int i = 0; i < TM; i++) {
        float s = 0.f, q = 0.f;
        #pragma unroll
        for (int j = 0; j < TN; j++) { s += o[i][j]; q += o[i][j] * o[i][j]; }
        s = wsum(s); q = wsum(q);   // lanes cover all 256 cols (two 4-col groups)
        float mean = s * (1.0f / DD);
        float var = q * (1.0f / DD) - mean * mean;
        float rstd = rsqrtf(var + 1e-5f);
        int gr = sPerm[m0 + i];
        if (gr >= 0) {
            float4 s0, s1;
            s0.x = (o[i][0] - mean) * rstd * gv[0] + lbv[0];
            s0.y = (o[i][1] - mean) * rstd * gv[1] + lbv[1];
            s0.z = (o[i][2] - mean) * rstd * gv[2] + lbv[2];
            s0.w = (o[i][3] - mean) * rstd * gv[3] + lbv[3];
            s1.x = (o[i][4] - mean) * rstd * gv[4] + lbv[4];
            s1.y = (o[i][5] - mean) * rstd * gv[5] + lbv[5];
            s1.z = (o[i][6] - mean) * rstd * gv[6] + lbv[6];
            s1.w = (o[i][7] - mean) * rstd * gv[7] + lbv[7];
            float* dst = C + (size_t)gr * BN;
            *(float4*)(dst + n0a) = s0;
            *(float4*)(dst + n0b) = s1;
        }
    }
}

// ---------------- plain SGEMM (decoder, no LN) ----------------
template <int BN, int TN, int RELU>
__global__ void __launch_bounds__(256, 2)
sgemm_dual(const float* __restrict__ A1, const float* __restrict__ A2,
           int K1, int K2,
           const float* __restrict__ B1, const float* __restrict__ B2,
           const float* __restrict__ bias, float* __restrict__ C,
           int M, int Nc) {
    const int BM = 128, BK = 16, TM = 8;
    const int NB4  = BN / 4;
    const int A_LD = 2;
    const int B_LD = (BK * BN / 4) / 256;
    __shared__ __align__(16) float As[BK][BM + 4];
    __shared__ __align__(16) float Bs[BK][BN];

    int tid = threadIdx.x;
    int brow0 = blockIdx.y * BM, bcol0 = blockIdx.x * BN;
    int tx = tid % (BN / TN), ty = tid / (BN / TN);
    int m0 = ty * TM, n0 = tx * TN;
    int t1 = K1 / BK, nt = (K1 + K2) / BK;

    float4 ar[A_LD], br[B_LD];
    u64 acc[TM][TN / 2];
    #pragma unroll
    for (int i = 0; i < TM; i++)
        #pragma unroll
        for (int j = 0; j < TN / 2; j++) acc[i][j] = 0ull;

#define LOAD_TILE(KT) {                                                        \
    const float* Ap; int lda, kofs;                                            \
    if ((KT) < t1) { Ap = A1; lda = K1; kofs = (KT) * BK; }                    \
    else           { Ap = A2; lda = K2; kofs = (KT) * BK - K1; }               \
    for (int i = 0; i < A_LD; i++) {                                           \
        int idx = tid + i * 256;                                               \
        int r = idx >> 2, c4 = idx & 3;                                        \
        int gr = brow0 + r;                                                    \
        ar[i] = (gr < M)                                                       \
              ? *(const float4*)(Ap + (size_t)gr * lda + kofs + c4 * 4)        \
              : make_float4(0.f, 0.f, 0.f, 0.f);                               \
    }                                                                          \
    const float* Bp = ((KT) < t1) ? B1 : B2;                                   \
    int bk0 = ((KT) < t1) ? (KT) * BK : (KT) * BK - K1;                        \
    for (int i = 0; i < B_LD; i++) {                                           \
        int idx = tid + i * 256;                                               \
        int r = idx / NB4, c4 = idx % NB4;                                     \
        br[i] = *(const float4*)(Bp + (size_t)(bk0 + r) * Nc + bcol0 + c4 * 4);\
    }                                                                          \
}

    LOAD_TILE(0);
    for (int kt = 0; kt < nt; kt++) {
        #pragma unroll
        for (int i = 0; i < A_LD; i++) {
            int idx = tid + i * 256;
            int r = idx >> 2, c4 = idx & 3;
            As[c4 * 4 + 0][r] = ar[i].x;
            As[c4 * 4 + 1][r] = ar[i].y;
            As[c4 * 4 + 2][r] = ar[i].z;
            As[c4 * 4 + 3][r] = ar[i].w;
        }
        #pragma unroll
        for (int i = 0; i < B_LD; i++) {
            int idx = tid + i * 256;
            int r = idx / NB4, c4 = idx % NB4;
            *(float4*)(&Bs[r][c4 * 4]) = br[i];
        }
        __syncthreads();
        if (kt + 1 < nt) { LOAD_TILE(kt + 1); }
        #pragma unroll
        for (int k = 0; k < BK; k++) {
            float4 av0 = *(const float4*)(&As[k][m0]);
            float4 av1 = *(const float4*)(&As[k][m0 + 4]);
            u64 b2[TN / 2];
            #pragma unroll
            for (int j = 0; j < TN / 4; j++) {
                float4 bv = *(const float4*)(&Bs[k][n0 + 4 * j]);
                b2[2 * j]     = pk2(bv.x, bv.y);
                b2[2 * j + 1] = pk2(bv.z, bv.w);
            }
            float a[8] = {av0.x, av0.y, av0.z, av0.w, av1.x, av1.y, av1.z, av1.w};
            #pragma unroll
            for (int i = 0; i < TM; i++) {
                u64 a2 = dup2(a[i]);
                #pragma unroll
                for (int j = 0; j < TN / 2; j++) ffma2(acc[i][j], a2, b2[j]);
            }
        }
        __syncthreads();
    }
#undef LOAD_TILE

    #pragma unroll
    for (int i = 0; i < TM; i++) {
        int gr = brow0 + m0 + i;
        if (gr < M) {
            float o[TN];
            #pragma unroll
            for (int j = 0; j < TN / 2; j++) {
                float2 p = up2(acc[i][j]);
                o[2 * j] = p.x; o[2 * j + 1] = p.y;
            }
            #pragma unroll
            for (int j = 0; j < TN; j++) {
                float v = o[j] + bias[bcol0 + n0 + j];
                if (RELU) v = fmaxf(v, 0.f);
                o[j] = v;
            }
            #pragma unroll
            for (int j = 0; j < TN / 4; j++) {
                float4 st = make_float4(o[4 * j], o[4 * j + 1],
                                        o[4 * j + 2], o[4 * j + 3]);
                *(float4*)(C + (size_t)gr * Nc + bcol0 + n0 + 4 * j) = st;
            }
        }
    }
}

// ---------------- launch ----------------
extern "C" void kernel_launch(void* const* d_in, const int* in_sizes, int n_in,
                              void* d_out, int out_size) {
    const float* x      = (const float*)d_in[0];
    const int*   ei     = (const int*)  d_in[1];
    const float* gum    = (const float*)d_in[2];
    const float* W_enc  = (const float*)d_in[3];
    const float* b_enc  = (const float*)d_in[4];
    const float* W_root = (const float*)d_in[5];
    const float* W_agg  = (const float*)d_in[6];
    const float* b_env  = (const float*)d_in[7];
    const float* Wir    = (const float*)d_in[8];
    const float* Wia    = (const float*)d_in[9];
    const float* bin    = (const float*)d_in[10];
    const float* Wor    = (const float*)d_in[11];
    const float* Woa    = (const float*)d_in[12];
    const float* bout   = (const float*)d_in[13];
    // d_in[14..16] = Wt_r, Wt_a, b_t : unused (temperature never affects argmax)
    const float* ln_g   = (const float*)d_in[17];
    const float* ln_b   = (const float*)d_in[18];
    const float* W_dec  = (const float*)d_in[19];
    const float* b_dec  = (const float*)d_in[20];
    float* out = (float*)d_out;

    void *phn, *pagg, *pcnt;
    cudaGetSymbolAddress(&phn,  g_hn);
    cudaGetSymbolAddress(&pagg, g_agg);
    cudaGetSymbolAddress(&pcnt, g_cnt);
    float* hnbuf  = (float*)phn;
    float* aggbuf = (float*)pagg;

    const int EB = (N_EDGES + 255) / 256;
    const int WB = (N_NODES + 7) / 8;          // warp-per-node kernels, 256 thr
    const int NB = (N_NODES + 255) / 256;
    const int GEMM_B = (N_NODES + 63) / 64;    // 782

    // CSR build
    cudaMemsetAsync(pcnt, 0, N_NODES * sizeof(int));
    k_hist<<<EB, 256>>>(ei);
    k_scan<<<1, 1024>>>();
    k_scatter<<<EB, 256>>>(ei);

    // encoder: hn = LN(relu(x @ W_enc + b_enc))   (identity row order)
    sgemm_ln<0><<<GEMM_B, 256>>>(x, nullptr, DIM_IN, 0,
                                 W_enc, nullptr, b_enc, ln_g, ln_b,
                                 hnbuf, N_NODES, /*use_perm=*/0);

    for (int l = 0; l < NLAYERS; l++) {
        k_act<<<296, 256>>>(Wir, Wia, Wor, Woa);   // also resets partition ctrs
        k_decide<<<NB, 256>>>(bin, bout, gum + (size_t)l * 2 * N_NODES * 2);
        k_agg_masked<<<WB, 256>>>();
        // hn = LN(relu([hn|agg] @ [W_root;W_agg] + b_env)), permuted + K-gated
        sgemm_ln<1><<<GEMM_B, 256>>>(hnbuf, aggbuf, DD, DD,
                                     W_root + (size_t)l * DD * DD,
                                     W_agg  + (size_t)l * DD * DD,
                                     b_env  + (size_t)l * DD, ln_g, ln_b,
                                     hnbuf, N_NODES, /*use_perm=*/1);
    }

    // decoder: out = hn @ W_dec + b_dec
    sgemm_dual<64, 4, 0><<<dim3(1, (N_NODES + 127) / 128), 256>>>(
        hnbuf, nullptr, DD, 0, W_dec, nullptr, b_dec, out, N_NODES, D_OUT);
}

// round 17
// speedup vs baseline: 1.1378x; 1.0612x over previous
#include <cuda_runtime.h>

#define N_NODES 50000
#define N_EDGES 800000
#define DIM_IN  128
#define DD      256
#define D_OUT   64
#define NLAYERS 3

typedef unsigned long long u64;

// ---------------- scratch (device globals; no allocations) ----------------
__device__ float g_hn [N_NODES * DD];   // layernormed activations (the only h)
__device__ float g_agg[N_NODES * DD];   // masked aggregation buffer
__device__ __align__(16) float g_pr[N_NODES * 8]; // [p_in0,p_in1,p_out0,p_out1,r_in0,r_in1,r_out0,r_out1]
__device__ int   g_rowptr[N_NODES + 1];
__device__ int   g_off[N_NODES];
__device__ int   g_cnt[N_NODES];
__device__ int   g_col[N_EDGES];
__device__ unsigned char g_in0 [N_NODES];
__device__ unsigned char g_out0[N_NODES];
__device__ int   g_perm[N_NODES];       // active nodes first, inactive after
__device__ int   g_nact;
__device__ int   g_ntail;

// ---------------- helpers ----------------
__device__ __forceinline__ u64 dup2(float x) {
    u64 r; unsigned u = __float_as_uint(x);
    asm("mov.b64 %0, {%1, %1};" : "=l"(r) : "r"(u));
    return r;
}
__device__ __forceinline__ float2 up2(u64 v) {
    unsigned lo, hi;
    asm("mov.b64 {%0, %1}, %2;" : "=r"(lo), "=r"(hi) : "l"(v));
    return make_float2(__uint_as_float(lo), __uint_as_float(hi));
}
__device__ __forceinline__ u64 pk2(float x, float y) {
    u64 r;
    asm("mov.b64 %0, {%1, %2};" : "=l"(r)
        : "r"(__float_as_uint(x)), "r"(__float_as_uint(y)));
    return r;
}
__device__ __forceinline__ void ffma2(u64& d, u64 a, u64 b) {
    asm("fma.rn.f32x2 %0, %1, %2, %0;" : "+l"(d) : "l"(a), "l"(b));
}
__device__ __forceinline__ float wsum(float v) {
    #pragma unroll
    for (int o = 16; o; o >>= 1) v += __shfl_xor_sync(0xffffffffu, v, o);
    return v;
}
__device__ __forceinline__ void cp16(unsigned dst, const float* src) {
    asm volatile("cp.async.cg.shared.global [%0], [%1], 16;"
                 :: "r"(dst), "l"(src) : "memory");
}
#define CP_COMMIT() asm volatile("cp.async.commit_group;" ::: "memory")
#define CP_WAIT0()  asm volatile("cp.async.wait_group 0;" ::: "memory")

// ---------------- CSR build ----------------
__global__ void k_hist(const int* __restrict__ ei) {
    int e = blockIdx.x * blockDim.x + threadIdx.x;
    if (e < N_EDGES) atomicAdd(&g_cnt[ei[e]], 1);
}
__global__ void k_scan() {
    __shared__ int s[1024];
    __shared__ int carry;
    int tid = threadIdx.x;
    if (tid == 0) carry = 0;
    __syncthreads();
    for (int start = 0; start < N_NODES; start += 1024) {
        int i = start + tid;
        int v = (i < N_NODES) ? g_cnt[i] : 0;
        s[tid] = v;
        __syncthreads();
        for (int o = 1; o < 1024; o <<= 1) {
            int t = (tid >= o) ? s[tid - o] : 0;
            __syncthreads();
            s[tid] += t;
            __syncthreads();
        }
        int base = carry;
        int excl = base + s[tid] - v;
        if (i < N_NODES) { g_rowptr[i] = excl; g_off[i] = excl; }
        int tot = s[1023];
        __syncthreads();
        if (tid == 0) carry = base + tot;
        __syncthreads();
    }
    if (threadIdx.x == 0) g_rowptr[N_NODES] = carry;
}
__global__ void k_scatter(const int* __restrict__ ei) {
    int e = blockIdx.x * blockDim.x + threadIdx.x;
    if (e < N_EDGES) {
        int u = ei[e];
        int v = ei[N_EDGES + e];
        int p = atomicAdd(&g_off[u], 1);
        g_col[p] = v;
    }
}

// ---------------- per-node action projections (8 scalars/node) ----------------
// Also resets the partition counters used by the following k_decide.
__global__ void __launch_bounds__(256)
k_act(const float* __restrict__ Wir, const float* __restrict__ Wia,
      const float* __restrict__ Wor, const float* __restrict__ Woa) {
    if (blockIdx.x == 0 && threadIdx.x == 0) { g_nact = 0; g_ntail = 0; }
    __shared__ float sW[8][DD];
    int tid = threadIdx.x;
    for (int j = tid; j < 2048; j += 256) {
        int which = j >> 9;             // 0:Wia 1:Woa 2:Wir 3:Wor
        int rem = j & 511;
        int k = rem >> 1, c = rem & 1;
        const float* src = (which == 0) ? Wia : (which == 1) ? Woa
                          : (which == 2) ? Wir : Wor;
        sW[which * 2 + c][k] = src[k * 2 + c];
    }
    __syncthreads();
    int lane = tid & 31;
    float wr[64];
    #pragma unroll
    for (int o = 0; o < 8; o++)
        #pragma unroll
        for (int i = 0; i < 8; i++)
            wr[o * 8 + i] = sW[o][lane + 32 * i];

    for (int node = blockIdx.x * 8 + (tid >> 5); node < N_NODES;
         node += gridDim.x * 8) {
        const float* hr = g_hn + (size_t)node * DD;
        float z[8];
        #pragma unroll
        for (int o = 0; o < 8; o++) z[o] = 0.f;
        #pragma unroll
        for (int i = 0; i < 8; i++) {
            float hv = hr[lane + 32 * i];
            #pragma unroll
            for (int o = 0; o < 8; o++) z[o] += hv * wr[o * 8 + i];
        }
        #pragma unroll
        for (int o = 0; o < 8; o++) z[o] = wsum(z[o]);
        if (lane == 0) {
            float* dst = g_pr + (size_t)node * 8;
            #pragma unroll
            for (int o = 0; o < 8; o++) dst[o] = z[o];
        }
    }
}

// ---------------- decisions + partition (fused) ----------------
// temp is a positive scalar -> never changes argmax; (hard+y-y) == hard to 2^-22.
__global__ void k_decide(const float* __restrict__ bin,
                         const float* __restrict__ bout,
                         const float* __restrict__ gl) {
    int u = blockIdx.x * blockDim.x + threadIdx.x;
    bool valid = (u < N_NODES);
    bool act = false;
    if (valid) {
        float sx = 0.f, sy = 0.f, sz = 0.f, sw = 0.f;
        int e0 = g_rowptr[u], e1 = g_rowptr[u + 1];
        for (int j = e0; j < e1; j++) {
            int v = g_col[j];
            float4 p = *(const float4*)(g_pr + (size_t)v * 8);
            sx += p.x; sy += p.y; sz += p.z; sw += p.w;
        }
        float4 r = *(const float4*)(g_pr + (size_t)u * 8 + 4);
        float a0 = r.x + sx + bin[0]  + gl[(size_t)u * 2 + 0];
        float a1 = r.y + sy + bin[1]  + gl[(size_t)u * 2 + 1];
        act = (a0 >= a1);                  // argmax ties -> first index
        g_in0[u] = act ? 1 : 0;
        float c0 = r.z + sz + bout[0] + gl[(size_t)2 * N_NODES + (size_t)u * 2 + 0];
        float c1 = r.w + sw + bout[1] + gl[(size_t)2 * N_NODES + (size_t)u * 2 + 1];
        g_out0[u] = (c0 >= c1) ? 1 : 0;
    }
    unsigned ma = __ballot_sync(0xffffffffu, valid && act);
    unsigned mi = __ballot_sync(0xffffffffu, valid && !act);
    int lane = threadIdx.x & 31;
    int na = __popc(ma), ni = __popc(mi);
    int ra = __popc(ma & ((1u << lane) - 1));
    int ri = __popc(mi & ((1u << lane) - 1));
    int base_a, base_i;
    if (lane == 0) base_a = atomicAdd(&g_nact, na);
    if (lane == 1) base_i = atomicAdd(&g_ntail, ni);
    base_a = __shfl_sync(0xffffffffu, base_a, 0);
    base_i = __shfl_sync(0xffffffffu, base_i, 1);
    if (valid) {
        if (act) g_perm[base_a + ra] = u;
        else     g_perm[N_NODES - 1 - (base_i + ri)] = u;
    }
}

// ---------------- masked aggregation (warp per node, CSR gather) ----------------
__global__ void k_agg_masked() {
    int u = (blockIdx.x * blockDim.x + threadIdx.x) >> 5;
    if (u >= N_NODES) return;
    int lane = threadIdx.x & 31;
    float4 a0 = make_float4(0.f, 0.f, 0.f, 0.f);
    float4 a1 = make_float4(0.f, 0.f, 0.f, 0.f);
    if (g_in0[u]) {
        int s = g_rowptr[u], e = g_rowptr[u + 1];
        for (int j = s; j < e; j++) {
            int v = g_col[j];
            if (!g_out0[v]) continue;
            const float4* p = (const float4*)(g_hn + (size_t)v * DD);
            float4 x0 = p[lane], x1 = p[lane + 32];
            a0.x += x0.x; a0.y += x0.y; a0.z += x0.z; a0.w += x0.w;
            a1.x += x1.x; a1.y += x1.y; a1.z += x1.z; a1.w += x1.w;
        }
    }
    float4* q = (float4*)(g_agg + (size_t)u * DD);
    q[lane] = a0; q[lane + 32] = a1;
}

// ---------------- SGEMM (FFMA2) fused bias+ReLU+LN, permuted rows, K-gated ----
// hn[perm] = LN( relu( [A1|A2][perm] @ [B1;B2] + bias ) )
// BM=64, BN=256(=Nc), BK=16, 2-stage buffer. B tile streamed with cp.async
// (no register staging, copy overlaps compute); A staged via regs (transpose).
// Race-safe ordering: writes to a buffer are issued only after the sync that
// retired its previous readers. GATED: blocks fully inside the inactive region
// (brow0 >= g_nact) skip the A2 k-range (agg rows there are exactly zero).
template <int GATED>
__global__ void __launch_bounds__(256, 2)
sgemm_ln(const float* __restrict__ A1, const float* __restrict__ A2,
         int K1, int K2,
         const float* __restrict__ B1, const float* __restrict__ B2,
         const float* __restrict__ bias,
         const float* __restrict__ gw, const float* __restrict__ gb,
         float* __restrict__ C, int M, int use_perm) {
    const int BM = 64, BN = 256, BK = 16, TM = 8, TN = 8;
    __shared__ __align__(16) float As[2][BK][BM + 4];
    __shared__ __align__(16) float Bs[2][BK][BN];
    __shared__ int sPerm[BM];
    __shared__ int sNt;

    int tid = threadIdx.x;
    int brow0 = blockIdx.x * BM;
    int tx = tid & 31, ty = tid >> 5;        // warp = fixed ty -> 8 rows
    int m0 = ty * TM;
    int n0a = tx * 4;                        // first 4-col group
    int n0b = 128 + tx * 4;                  // second 4-col group
    int t1 = K1 / BK;

    // B cp.async destination offsets (two stages), and source row/col
    int bidx_r[4], bidx_c[4];
    unsigned bDst[2][4];
    unsigned bsBase = (unsigned)__cvta_generic_to_shared(&Bs[0][0][0]);
    #pragma unroll
    for (int i = 0; i < 4; i++) {
        int idx = tid + i * 256;
        bidx_r[i] = idx >> 6;
        bidx_c[i] = (idx & 63) * 4;
        bDst[0][i] = bsBase + (unsigned)((bidx_r[i] * BN + bidx_c[i]) * 4);
        bDst[1][i] = bDst[0][i] + (unsigned)(BK * BN * 4);
    }

    if (tid < BM) {
        int gi = brow0 + tid;
        sPerm[tid] = (gi < M) ? (use_perm ? g_perm[gi] : gi) : -1;
    }
    if (tid == 0) {
        int full = (K1 + K2) / BK;
        sNt = (GATED && brow0 >= g_nact) ? t1 : full;
    }
    __syncthreads();
    int nt = sNt;

    int arow = sPerm[tid >> 2];          // this thread's A gather row
    int ac4  = (tid & 3) * 4;            // k-offset within tile

    float4 ar;
    u64 acc[TM][TN / 2];
    #pragma unroll
    for (int i = 0; i < TM; i++)
        #pragma unroll
        for (int j = 0; j < TN / 2; j++) acc[i][j] = 0ull;

#define LOAD_A(KT) {                                                           \
    const float* Ap; int lda, kofs;                                            \
    if ((KT) < t1) { Ap = A1; lda = K1; kofs = (KT) * BK; }                    \
    else           { Ap = A2; lda = K2; kofs = (KT) * BK - K1; }               \
    ar = (arow >= 0)                                                           \
       ? *(const float4*)(Ap + (size_t)arow * lda + kofs + ac4)                \
       : make_float4(0.f, 0.f, 0.f, 0.f);                                      \
}

#define LOAD_B_ASYNC(KT, S) {                                                  \
    const float* Bp = ((KT) < t1) ? B1 : B2;                                   \
    int bk0 = ((KT) < t1) ? (KT) * BK : (KT) * BK - K1;                        \
    for (int i = 0; i < 4; i++)                                                \
        cp16(bDst[S][i], Bp + (size_t)(bk0 + bidx_r[i]) * BN + bidx_c[i]);     \
    CP_COMMIT();                                                               \
}

#define STORE_A(S) {                                                           \
    int r = tid >> 2;                                                          \
    As[S][ac4 + 0][r] = ar.x;                                                  \
    As[S][ac4 + 1][r] = ar.y;                                                  \
    As[S][ac4 + 2][r] = ar.z;                                                  \
    As[S][ac4 + 3][r] = ar.w;                                                  \
}

    // prologue: tile 0 in flight
    LOAD_A(0);
    LOAD_B_ASYNC(0, 0);

    for (int kt = 0; kt < nt; kt++) {
        int sb = kt & 1;
        STORE_A(sb);
        CP_WAIT0();                 // B(kt) landed (this thread's copies)
        __syncthreads();            // all threads' As/Bs for kt visible
        if (kt + 1 < nt) {          // issue next tile into the freed buffer
            LOAD_A(kt + 1);
            LOAD_B_ASYNC(kt + 1, 1 - sb);
        }
        #pragma unroll
        for (int k = 0; k < BK; k++) {
            float4 av0 = *(const float4*)(&As[sb][k][m0]);
            float4 av1 = *(const float4*)(&As[sb][k][m0 + 4]);
            ulonglong2 bv0 = *(const ulonglong2*)(&Bs[sb][k][n0a]);
            ulonglong2 bv1 = *(const ulonglong2*)(&Bs[sb][k][n0b]);
            u64 b2[4] = {bv0.x, bv0.y, bv1.x, bv1.y};
            float a[8] = {av0.x, av0.y, av0.z, av0.w, av1.x, av1.y, av1.z, av1.w};
            #pragma unroll
            for (int i = 0; i < TM; i++) {
                u64 a2 = dup2(a[i]);
                #pragma unroll
                for (int j = 0; j < TN / 2; j++) ffma2(acc[i][j], a2, b2[j]);
            }
        }
    }
#undef LOAD_A
#undef LOAD_B_ASYNC
#undef STORE_A

    // ---- epilogue: bias + relu + LayerNorm (single-pass mean/var) ----
    float4 bi0 = *(const float4*)(bias + n0a);
    float4 bi1 = *(const float4*)(bias + n0b);
    float bb[8] = {bi0.x, bi0.y, bi0.z, bi0.w, bi1.x, bi1.y, bi1.z, bi1.w};
    float4 gg0 = *(const float4*)(gw + n0a);
    float4 gg1 = *(const float4*)(gw + n0b);
    float gv[8] = {gg0.x, gg0.y, gg0.z, gg0.w, gg1.x, gg1.y, gg1.z, gg1.w};
    float4 lb0 = *(const float4*)(gb + n0a);
    float4 lb1 = *(const float4*)(gb + n0b);
    float lbv[8] = {lb0.x, lb0.y, lb0.z, lb0.w, lb1.x, lb1.y, lb1.z, lb1.w};

    float o[TM][TN];
    #pragma unroll
    for (int i = 0; i < TM; i++) {
        #pragma unroll
        for (int j = 0; j < TN / 2; j++) {
            float2 p = up2(acc[i][j]);
            o[i][2 * j] = p.x; o[i][2 * j + 1] = p.y;
        }
        #pragma unroll
        for (int j = 0; j < TN; j++)
            o[i][j] = fmaxf(o[i][j] + bb[j], 0.f);
    }

    #pragma unroll
    for (int i = 0; i < TM; i++) {
        float s = 0.f, q = 0.f;
        #pragma unroll
        for (int j = 0; j < TN; j++) { s += o[i][j]; q += o[i][j] * o[i][j]; }
        s = wsum(s); q = wsum(q);   // lanes cover all 256 cols (two 4-col groups)
        float mean = s * (1.0f / DD);
        float var = q * (1.0f / DD) - mean * mean;
        float rstd = rsqrtf(var + 1e-5f);
        int gr = sPerm[m0 + i];
        if (gr >= 0) {
            float4 s0, s1;
            s0.x = (o[i][0] - mean) * rstd * gv[0] + lbv[0];
            s0.y = (o[i][1] - mean) * rstd * gv[1] + lbv[1];
            s0.z = (o[i][2] - mean) * rstd * gv[2] + lbv[2];
            s0.w = (o[i][3] - mean) * rstd * gv[3] + lbv[3];
            s1.x = (o[i][4] - mean) * rstd * gv[4] + lbv[4];
            s1.y = (o[i][5] - mean) * rstd * gv[5] + lbv[5];
            s1.z = (o[i][6] - mean) * rstd * gv[6] + lbv[6];
            s1.w = (o[i][7] - mean) * rstd * gv[7] + lbv[7];
            float* dst = C + (size_t)gr * BN;
            *(float4*)(dst + n0a) = s0;
            *(float4*)(dst + n0b) = s1;
        }
    }
}

// ---------------- plain SGEMM (decoder, no LN) ----------------
template <int BN, int TN, int RELU>
__global__ void __launch_bounds__(256, 2)
sgemm_dual(const float* __restrict__ A1, const float* __restrict__ A2,
           int K1, int K2,
           const float* __restrict__ B1, const float* __restrict__ B2,
           const float* __restrict__ bias, float* __restrict__ C,
           int M, int Nc) {
    const int BM = 128, BK = 16, TM = 8;
    const int NB4  = BN / 4;
    const int A_LD = 2;
    const int B_LD = (BK * BN / 4) / 256;
    __shared__ __align__(16) float As[BK][BM + 4];
    __shared__ __align__(16) float Bs[BK][BN];

    int tid = threadIdx.x;
    int brow0 = blockIdx.y * BM, bcol0 = blockIdx.x * BN;
    int tx = tid % (BN / TN), ty = tid / (BN / TN);
    int m0 = ty * TM, n0 = tx * TN;
    int t1 = K1 / BK, nt = (K1 + K2) / BK;

    float4 ar[A_LD], br[B_LD];
    u64 acc[TM][TN / 2];
    #pragma unroll
    for (int i = 0; i < TM; i++)
        #pragma unroll
        for (int j = 0; j < TN / 2; j++) acc[i][j] = 0ull;

#define LOAD_TILE(KT) {                                                        \
    const float* Ap; int lda, kofs;                                            \
    if ((KT) < t1) { Ap = A1; lda = K1; kofs = (KT) * BK; }                    \
    else           { Ap = A2; lda = K2; kofs = (KT) * BK - K1; }               \
    for (int i = 0; i < A_LD; i++) {                                           \
        int idx = tid + i * 256;                                               \
        int r = idx >> 2, c4 = idx & 3;                                        \
        int gr = brow0 + r;                                                    \
        ar[i] = (gr < M)                                                       \
              ? *(const float4*)(Ap + (size_t)gr * lda + kofs + c4 * 4)        \
              : make_float4(0.f, 0.f, 0.f, 0.f);                               \
    }                                                                          \
    const float* Bp = ((KT) < t1) ? B1 : B2;                                   \
    int bk0 = ((KT) < t1) ? (KT) * BK : (KT) * BK - K1;                        \
    for (int i = 0; i < B_LD; i++) {                                           \
        int idx = tid + i * 256;                                               \
        int r = idx / NB4, c4 = idx % NB4;                                     \
        br[i] = *(const float4*)(Bp + (size_t)(bk0 + r) * Nc + bcol0 + c4 * 4);\
    }                                                                          \
}

    LOAD_TILE(0);
    for (int kt = 0; kt < nt; kt++) {
        #pragma unroll
        for (int i = 0; i < A_LD; i++) {
            int idx = tid + i * 256;
            int r = idx >> 2, c4 = idx & 3;
            As[c4 * 4 + 0][r] = ar[i].x;
            As[c4 * 4 + 1][r] = ar[i].y;
            As[c4 * 4 + 2][r] = ar[i].z;
            As[c4 * 4 + 3][r] = ar[i].w;
        }
        #pragma unroll
        for (int i = 0; i < B_LD; i++) {
            int idx = tid + i * 256;
            int r = idx / NB4, c4 = idx % NB4;
            *(float4*)(&Bs[r][c4 * 4]) = br[i];
        }
        __syncthreads();
        if (kt + 1 < nt) { LOAD_TILE(kt + 1); }
        #pragma unroll
        for (int k = 0; k < BK; k++) {
            float4 av0 = *(const float4*)(&As[k][m0]);
            float4 av1 = *(const float4*)(&As[k][m0 + 4]);
            u64 b2[TN / 2];
            #pragma unroll
            for (int j = 0; j < TN / 4; j++) {
                float4 bv = *(const float4*)(&Bs[k][n0 + 4 * j]);
                b2[2 * j]     = pk2(bv.x, bv.y);
                b2[2 * j + 1] = pk2(bv.z, bv.w);
            }
            float a[8] = {av0.x, av0.y, av0.z, av0.w, av1.x, av1.y, av1.z, av1.w};
            #pragma unroll
            for (int i = 0; i < TM; i++) {
                u64 a2 = dup2(a[i]);
                #pragma unroll
                for (int j = 0; j < TN / 2; j++) ffma2(acc[i][j], a2, b2[j]);
            }
        }
        __syncthreads();
    }
#undef LOAD_TILE

    #pragma unroll
    for (int i = 0; i < TM; i++) {
        int gr = brow0 + m0 + i;
        if (gr < M) {
            float o[TN];
            #pragma unroll
            for (int j = 0; j < TN / 2; j++) {
                float2 p = up2(acc[i][j]);
                o[2 * j] = p.x; o[2 * j + 1] = p.y;
            }
            #pragma unroll
            for (int j = 0; j < TN; j++) {
                float v = o[j] + bias[bcol0 + n0 + j];
                if (RELU) v = fmaxf(v, 0.f);
                o[j] = v;
            }
            #pragma unroll
            for (int j = 0; j < TN / 4; j++) {
                float4 st = make_float4(o[4 * j], o[4 * j + 1],
                                        o[4 * j + 2], o[4 * j + 3]);
                *(float4*)(C + (size_t)gr * Nc + bcol0 + n0 + 4 * j) = st;
            }
        }
    }
}

// ---------------- launch ----------------
extern "C" void kernel_launch(void* const* d_in, const int* in_sizes, int n_in,
                              void* d_out, int out_size) {
    const float* x      = (const float*)d_in[0];
    const int*   ei     = (const int*)  d_in[1];
    const float* gum    = (const float*)d_in[2];
    const float* W_enc  = (const float*)d_in[3];
    const float* b_enc  = (const float*)d_in[4];
    const float* W_root = (const float*)d_in[5];
    const float* W_agg  = (const float*)d_in[6];
    const float* b_env  = (const float*)d_in[7];
    const float* Wir    = (const float*)d_in[8];
    const float* Wia    = (const float*)d_in[9];
    const float* bin    = (const float*)d_in[10];
    const float* Wor    = (const float*)d_in[11];
    const float* Woa    = (const float*)d_in[12];
    const float* bout   = (const float*)d_in[13];
    // d_in[14..16] = Wt_r, Wt_a, b_t : unused (temperature never affects argmax)
    const float* ln_g   = (const float*)d_in[17];
    const float* ln_b   = (const float*)d_in[18];
    const float* W_dec  = (const float*)d_in[19];
    const float* b_dec  = (const float*)d_in[20];
    float* out = (float*)d_out;

    void *phn, *pagg, *pcnt;
    cudaGetSymbolAddress(&phn,  g_hn);
    cudaGetSymbolAddress(&pagg, g_agg);
    cudaGetSymbolAddress(&pcnt, g_cnt);
    float* hnbuf  = (float*)phn;
    float* aggbuf = (float*)pagg;

    const int EB = (N_EDGES + 255) / 256;
    const int WB = (N_NODES + 7) / 8;          // warp-per-node kernels, 256 thr
    const int NB = (N_NODES + 255) / 256;
    const int GEMM_B = (N_NODES + 63) / 64;    // 782

    // CSR build
    cudaMemsetAsync(pcnt, 0, N_NODES * sizeof(int));
    k_hist<<<EB, 256>>>(ei);
    k_scan<<<1, 1024>>>();
    k_scatter<<<EB, 256>>>(ei);

    // encoder: hn = LN(relu(x @ W_enc + b_enc))   (identity row order)
    sgemm_ln<0><<<GEMM_B, 256>>>(x, nullptr, DIM_IN, 0,
                                 W_enc, nullptr, b_enc, ln_g, ln_b,
                                 hnbuf, N_NODES, /*use_perm=*/0);

    for (int l = 0; l < NLAYERS; l++) {
        k_act<<<296, 256>>>(Wir, Wia, Wor, Woa);   // also resets partition ctrs
        k_decide<<<NB, 256>>>(bin, bout, gum + (size_t)l * 2 * N_NODES * 2);
        k_agg_masked<<<WB, 256>>>();
        // hn = LN(relu([hn|agg] @ [W_root;W_agg] + b_env)), permuted + K-gated
        sgemm_ln<1><<<GEMM_B, 256>>>(hnbuf, aggbuf, DD, DD,
                                     W_root + (size_t)l * DD * DD,
                                     W_agg  + (size_t)l * DD * DD,
                                     b_env  + (size_t)l * DD, ln_g, ln_b,
                                     hnbuf, N_NODES, /*use_perm=*/1);
    }

    // decoder: out = hn @ W_dec + b_dec
    sgemm_dual<64, 4, 0><<<dim3(1, (N_NODES + 127) / 128), 256>>>(
        hnbuf, nullptr, DD, 0, W_dec, nullptr, b_dec, out, N_NODES, D_OUT);
}